// round 1
// baseline (speedup 1.0000x reference)
#include <cuda_runtime.h>
#include <cstdint>

#define Nn    100000
#define F     256
#define FS    32
#define FA    288
#define NLY   4
#define NG    50
#define NE_UP 400000
#define NE_L  300000

// ---------------- device scratch (allocation-free rule: __device__ globals) ----------------
__device__ float g_x[(size_t)Nn * F];       // current node features [N,256]
__device__ float g_pi[(size_t)Nn * F];      // partial_inner buffer  [N,256]
__device__ float g_agg[(size_t)Nn * FA];    // aggregation scratch   [N,288]
__device__ float g_agg16[(size_t)Nn * 16];  // up-conv aggregation   [N,16]
__device__ float g_dinv[(size_t)9 * Nn];    // per-edge-set D^{-1/2}: slot 0 = up, 1..4 inner, 5..8 fw
__device__ int   g_rows[(size_t)NLY * Nn];  // per-layer row lists
__device__ int   g_cnt[NLY];

// vectorized float atomic reduction (sm_90+)
__device__ __forceinline__ void red_add_v4(float* addr, float4 v) {
    asm volatile("red.global.add.v4.f32 [%0], {%1,%2,%3,%4};"
                 :: "l"(addr), "f"(v.x), "f"(v.y), "f"(v.z), "f"(v.w)
                 : "memory");
}

// ---------------- degree / dinv ----------------
__global__ void k_deg_init() {
    int i = blockIdx.x * blockDim.x + threadIdx.x;
    if (i < 9 * Nn) g_dinv[i] = 1.0f;     // self-loop contributes 1 to every deg
    if (i < NLY) g_cnt[i] = 0;
}

__global__ void k_deg_count(const int* __restrict__ dst, int nE, int slot) {
    int i = blockIdx.x * blockDim.x + threadIdx.x;
    if (i >= nE) return;
    atomicAdd(&g_dinv[(size_t)slot * Nn + dst[i]], 1.0f);
}

__global__ void k_rsqrt() {
    int i = blockIdx.x * blockDim.x + threadIdx.x;
    if (i < 9 * Nn) g_dinv[i] = rsqrtf(g_dinv[i]);
}

__global__ void k_build(const int* __restrict__ layers) {
    int n = blockIdx.x * blockDim.x + threadIdx.x;
    if (n >= Nn) return;
    int il = layers[n];             // always in [0, NLY)
    int p = atomicAdd(&g_cnt[il], 1);
    g_rows[(size_t)il * Nn + p] = n;
}

// ---------------- up conv (x16 -> 256) ----------------
__global__ void k_up_init(const float* __restrict__ x16) {
    int i = blockIdx.x * blockDim.x + threadIdx.x;
    if (i >= Nn * 16) return;
    int n = i >> 4;
    float di = g_dinv[n];
    g_agg16[i] = x16[i] * di * di;
}

__global__ void k_up_scatter(const int* __restrict__ es, const int* __restrict__ ed,
                             const float* __restrict__ x16) {
    int i = blockIdx.x * blockDim.x + threadIdx.x;
    if (i >= NE_UP * 4) return;
    int e = i >> 2, q = i & 3;
    int s = es[e], d = ed[e];
    float norm = g_dinv[s] * g_dinv[d];
    float4 v = ((const float4*)(x16 + (size_t)s * 16))[q];
    v.x *= norm; v.y *= norm; v.z *= norm; v.w *= norm;
    red_add_v4(g_agg16 + (size_t)d * 16 + q * 4, v);
}

__global__ void k_up_gemm(const float* __restrict__ Wup, const float* __restrict__ bup) {
    __shared__ float sW[16 * 256];
    __shared__ float sA[32 * 16];
    int tid = threadIdx.x;   // 256 threads, one output column each
#pragma unroll
    for (int r = 0; r < 16; r++) sW[tid + r * 256] = Wup[tid + r * 256];
    int row0 = blockIdx.x * 32;
    for (int e = tid; e < 512; e += 256) {
        int m = e >> 4, k = e & 15;
        int n = row0 + m;
        sA[e] = (n < Nn) ? g_agg16[(size_t)n * 16 + k] : 0.f;
    }
    __syncthreads();
    float bj = bup[tid];
    for (int m = 0; m < 32; m++) {
        int n = row0 + m;
        if (n >= Nn) break;
        float acc = bj;
#pragma unroll
        for (int k = 0; k < 16; k++) acc += sA[m * 16 + k] * sW[k * 256 + tid];
        g_x[(size_t)n * 256 + tid] = acc;
    }
}

// ---------------- generic conv: init / scatter / gemm ----------------
// blockDim = 288 : 4 rows x 72 float4 chunks
__global__ void k_agg_init(const float* __restrict__ stat, int dslot, int mask_il) {
    int tid = threadIdx.x;
    int c = tid % 72, r = tid / 72;
    int idx = blockIdx.x * 4 + r;
    int cnt = (mask_il >= 0) ? g_cnt[mask_il] : Nn;
    if (idx >= cnt) return;
    int n = (mask_il >= 0) ? g_rows[(size_t)mask_il * Nn + idx] : idx;
    float di = g_dinv[(size_t)dslot * Nn + n];
    float s = di * di;
    float4 v = (c < 64) ? ((const float4*)(g_x + (size_t)n * F))[c]
                        : ((const float4*)(stat + (size_t)n * FS))[c - 64];
    v.x *= s; v.y *= s; v.z *= s; v.w *= s;
    ((float4*)(g_agg + (size_t)n * FA))[c] = v;
}

// one warp per edge
__global__ void k_scatter(const int* __restrict__ es, const int* __restrict__ ed,
                          int dslot, const float* __restrict__ stat,
                          const int* __restrict__ layers, int mask_il) {
    int w = (blockIdx.x * blockDim.x + threadIdx.x) >> 5;
    int lane = threadIdx.x & 31;
    if (w >= NE_L) return;
    int d = ed[w];
    if (mask_il >= 0 && layers[d] != mask_il) return;
    int s = es[w];
    const float* dinv = g_dinv + (size_t)dslot * Nn;
    float norm = dinv[s] * dinv[d];
    const float4* xs = (const float4*)(g_x + (size_t)s * F);
    const float4* ss = (const float4*)(stat + (size_t)s * FS);
    float* aggd = g_agg + (size_t)d * FA;
    for (int c = lane; c < 72; c += 32) {
        float4 v = (c < 64) ? xs[c] : ss[c - 64];
        v.x *= norm; v.y *= norm; v.z *= norm; v.w *= norm;
        red_add_v4(aggd + c * 4, v);
    }
}

// fp32 tiled GEMM with row indirection: out[rows] = agg[rows,288] @ W[288,256] + b
// BM=64 BN=128 BK=16, 256 threads, 8x4 micro-tile
__global__ void k_gemm(int mask_il, const float* __restrict__ W,
                       const float* __restrict__ b, int to_pi) {
    __shared__ float As[64][16];
    __shared__ float Bs[16][128];
    int cnt = (mask_il >= 0) ? g_cnt[mask_il] : Nn;
    const int* list = (mask_il >= 0) ? (g_rows + (size_t)mask_il * Nn) : nullptr;
    int row0 = blockIdx.x * 64;
    if (row0 >= cnt) return;
    int col0 = blockIdx.y * 128;
    int tid = threadIdx.x;
    int tx = tid & 31, ty = tid >> 5;

    float acc[8][4];
#pragma unroll
    for (int i = 0; i < 8; i++)
#pragma unroll
        for (int j = 0; j < 4; j++) acc[i][j] = 0.f;

    int lk = tid & 15;
    int lrow[4];
#pragma unroll
    for (int r = 0; r < 4; r++) {
        int m = r * 16 + (tid >> 4);
        int g = row0 + m;
        lrow[r] = (g < cnt) ? (list ? list[g] : g) : -1;
    }

    for (int kt = 0; kt < FA; kt += 16) {
#pragma unroll
        for (int r = 0; r < 4; r++) {
            int m = r * 16 + (tid >> 4);
            int n = lrow[r];
            As[m][lk] = (n >= 0) ? g_agg[(size_t)n * FA + kt + lk] : 0.f;
        }
#pragma unroll
        for (int r = 0; r < 8; r++) {
            int elem = tid + r * 256;
            int k = elem >> 7, j = elem & 127;
            Bs[k][j] = W[(size_t)(kt + k) * F + col0 + j];
        }
        __syncthreads();
#pragma unroll
        for (int kk = 0; kk < 16; kk++) {
            float4 bv = *(const float4*)(&Bs[kk][tx * 4]);
#pragma unroll
            for (int i = 0; i < 8; i++) {
                float a = As[ty * 8 + i][kk];
                acc[i][0] += a * bv.x;
                acc[i][1] += a * bv.y;
                acc[i][2] += a * bv.z;
                acc[i][3] += a * bv.w;
            }
        }
        __syncthreads();
    }
    float* outbase = to_pi ? g_pi : g_x;
    float4 bb = *(const float4*)(&b[col0 + tx * 4]);
#pragma unroll
    for (int i = 0; i < 8; i++) {
        int g = row0 + ty * 8 + i;
        if (g >= cnt) break;
        int n = list ? list[g] : g;
        float4 v = make_float4(acc[i][0] + bb.x, acc[i][1] + bb.y,
                               acc[i][2] + bb.z, acc[i][3] + bb.w);
        *(float4*)(outbase + (size_t)n * F + col0 + tx * 4) = v;
    }
}

// ---------------- misc ----------------
__global__ void k_copy_rows(int il) {   // x[rows(il)] = pi[rows(il)]   (256 threads = 4 rows x 64 f4)
    int c = threadIdx.x % 64, r = threadIdx.x / 64;
    int idx = blockIdx.x * 4 + r;
    if (idx >= g_cnt[il]) return;
    int n = g_rows[(size_t)il * Nn + idx];
    ((float4*)(g_x + (size_t)n * F))[c] = ((const float4*)(g_pi + (size_t)n * F))[c];
}

__global__ void k_relu() {
    int i = blockIdx.x * blockDim.x + threadIdx.x;
    if (i < Nn * F) g_x[i] = fmaxf(g_x[i], 0.f);
}

__global__ void k_pool_init(const float* __restrict__ bl, float* __restrict__ out) {
    int g = threadIdx.x;
    if (g < NG) out[g] = bl[0];
}

__global__ void k_pool(const int* __restrict__ batch, const float* __restrict__ Wl,
                       float* __restrict__ out) {
    int w = (blockIdx.x * blockDim.x + threadIdx.x) >> 5;
    int lane = threadIdx.x & 31;
    if (w >= Nn) return;
    const float* xr = g_x + (size_t)w * F;
    float s = 0.f;
    for (int c = lane; c < F; c += 32) s += xr[c] * Wl[c];
#pragma unroll
    for (int o = 16; o; o >>= 1) s += __shfl_down_sync(0xffffffffu, s, o);
    if (lane == 0) atomicAdd(&out[batch[w]], s);
}

// ---------------- orchestration ----------------
extern "C" void kernel_launch(void* const* d_in, const int* in_sizes, int n_in,
                              void* d_out, int out_size) {
    const float* x16    = (const float*)d_in[0];
    const float* stat   = (const float*)d_in[1];
    const int*   eidx   = (const int*)d_in[2];
    const int*   einner = (const int*)d_in[3];
    const int*   efw    = (const int*)d_in[4];
    // d_in[5] (backward_edges) is dead in the reference
    const int*   layers = (const int*)d_in[6];
    const int*   batch  = (const int*)d_in[7];
    const float* W_up  = (const float*)d_in[8];
    const float* b_up  = (const float*)d_in[9];
    const float* W_in  = (const float*)d_in[10];
    const float* b_in  = (const float*)d_in[11];
    const float* W_fw  = (const float*)d_in[12];
    const float* b_fw  = (const float*)d_in[13];
    const float* W_lin = (const float*)d_in[14];
    const float* b_lin = (const float*)d_in[15];
    float* out = (float*)d_out;

    // ---- per-edge-set dinv + row lists (cheap; recomputed every call) ----
    k_deg_init<<<(9 * Nn + 255) / 256, 256>>>();
    k_deg_count<<<(NE_UP + 255) / 256, 256>>>(eidx + NE_UP, NE_UP, 0);
    for (int il = 0; il < NLY; il++)
        k_deg_count<<<(NE_L + 255) / 256, 256>>>(einner + (size_t)il * 2 * NE_L + NE_L, NE_L, 1 + il);
    for (int il = 0; il < NLY; il++)
        k_deg_count<<<(NE_L + 255) / 256, 256>>>(efw + (size_t)il * 2 * NE_L + NE_L, NE_L, 5 + il);
    k_rsqrt<<<(9 * Nn + 255) / 256, 256>>>();
    k_build<<<(Nn + 255) / 256, 256>>>(layers);

    // ---- up conv (all rows) ----
    k_up_init<<<(Nn * 16 + 255) / 256, 256>>>(x16);
    k_up_scatter<<<(NE_UP * 4 + 255) / 256, 256>>>(eidx, eidx + NE_UP, x16);
    k_up_gemm<<<(Nn + 31) / 32, 256>>>(W_up, b_up);

    const int GEMM_GX = (Nn + 63) / 64;
    auto conv = [&](const int* es, const int* ed, int dslot, int mask,
                    const float* W, const float* bb, int to_pi) {
        k_agg_init<<<(Nn + 3) / 4, 288>>>(stat, dslot, mask);
        k_scatter<<<(NE_L * 32 + 255) / 256, 256>>>(es, ed, dslot, stat, layers, mask);
        k_gemm<<<dim3(GEMM_GX, 2), 256>>>(mask, W, bb, to_pi);
    };
    auto in_src = [&](int il) { return einner + (size_t)il * 2 * NE_L; };
    auto fw_src = [&](int il) { return efw + (size_t)il * 2 * NE_L; };

    for (int p = 0; p < 2; p++) {
        // forward sweep
        for (int il = 0; il < 3; il++) {
            conv(in_src(il), in_src(il) + NE_L, 1 + il, il, W_in, b_in, 0);         // inner -> rows(il)
            conv(fw_src(il), fw_src(il) + NE_L, 5 + il, il + 1, W_fw, b_fw, 0);     // fw    -> rows(il+1)
        }
        conv(in_src(3), in_src(3) + NE_L, 4, -1, W_in, b_in, 1);                    // inner il=3, FULL -> pi
        k_copy_rows<<<(Nn + 3) / 4, 256>>>(3);                                      // x[rows(3)] = pi
        // fw il=3 writes layers==4: empty, skipped
        k_relu<<<(Nn * F + 255) / 256, 256>>>();
        // backward sweep (uses stale pi from forward il=3)
        for (int il = 3; il >= 0; il--) {
            if (il >= 1) k_copy_rows<<<(Nn + 3) / 4, 256>>>(il - 1);                // x[rows(il-1)] = pi
            conv(in_src(il), in_src(il) + NE_L, 1 + il, il, W_in, b_in, 0);         // inner -> rows(il)
        }
        k_relu<<<(Nn * F + 255) / 256, 256>>>();
    }

    // ---- pool + linear head ----
    k_pool_init<<<1, 64>>>(b_lin, out);
    k_pool<<<(Nn * 32 + 255) / 256, 256>>>(batch, W_lin, out);
}

// round 3
// speedup vs baseline: 1.4561x; 1.4561x over previous
#include <cuda_runtime.h>
#include <cstdint>

#define Nn    100000
#define F     256
#define FS    32
#define FA    288
#define NLY   4
#define NG    50
#define NE_UP 400000
#define NE_L  300000

// ---------------- device scratch ----------------
__device__ float g_x[(size_t)Nn * F];
__device__ float g_pi[(size_t)Nn * F];
__device__ float g_agg[(size_t)Nn * FA];
__device__ float g_agg16[(size_t)Nn * 16];
__device__ float g_dinv[(size_t)9 * Nn];
__device__ int   g_rows[(size_t)NLY * Nn];
__device__ int   g_cnt[NLY];
__device__ float g_WtIn[(size_t)256 * FA];   // W_in^T  [256,288] (col-major B)
__device__ float g_WtFw[(size_t)256 * FA];   // W_fw^T  [256,288]
__device__ float g_WtUp[(size_t)256 * 16];   // W_up^T  [256,16]

__device__ __forceinline__ uint32_t f2tf32(float f) {
    uint32_t r; asm("cvt.rna.tf32.f32 %0, %1;" : "=r"(r) : "f"(f)); return r;
}
__device__ __forceinline__ void red_add_v4(float* addr, float4 v) {
    asm volatile("red.global.add.v4.f32 [%0], {%1,%2,%3,%4};"
                 :: "l"(addr), "f"(v.x), "f"(v.y), "f"(v.z), "f"(v.w) : "memory");
}
__device__ __forceinline__ void mma_tf32(float* d, const uint32_t* a, const uint32_t* b) {
    asm volatile(
        "mma.sync.aligned.m16n8k8.row.col.f32.tf32.tf32.f32 "
        "{%0,%1,%2,%3}, {%4,%5,%6,%7}, {%8,%9}, {%0,%1,%2,%3};"
        : "+f"(d[0]), "+f"(d[1]), "+f"(d[2]), "+f"(d[3])
        : "r"(a[0]), "r"(a[1]), "r"(a[2]), "r"(a[3]), "r"(b[0]), "r"(b[1]));
}

// ---------------- degree / dinv / rows ----------------
__global__ void k_deg_init() {
    int i = blockIdx.x * blockDim.x + threadIdx.x;
    if (i < 9 * Nn) g_dinv[i] = 1.0f;
    if (i < NLY) g_cnt[i] = 0;
}
__global__ void k_deg_count(const int* __restrict__ dst, int nE, int slot) {
    int i = blockIdx.x * blockDim.x + threadIdx.x;
    if (i >= nE) return;
    atomicAdd(&g_dinv[(size_t)slot * Nn + dst[i]], 1.0f);
}
__global__ void k_rsqrt() {
    int i = blockIdx.x * blockDim.x + threadIdx.x;
    if (i < 9 * Nn) g_dinv[i] = rsqrtf(g_dinv[i]);
}
__global__ void k_build(const int* __restrict__ layers) {
    int n = blockIdx.x * blockDim.x + threadIdx.x;
    if (n >= Nn) return;
    int il = layers[n];
    int p = atomicAdd(&g_cnt[il], 1);
    g_rows[(size_t)il * Nn + p] = n;
}
__global__ void k_transpose(const float* __restrict__ W, float* __restrict__ Wt, int K) {
    int i = blockIdx.x * blockDim.x + threadIdx.x;   // W[K,256]
    if (i >= K * 256) return;
    int k = i >> 8, n = i & 255;
    Wt[(size_t)n * K + k] = W[i];
}

// ---------------- up conv aggregation ----------------
__global__ void k_up_init(const float* __restrict__ x16) {
    int i = blockIdx.x * blockDim.x + threadIdx.x;
    if (i >= Nn * 16) return;
    int n = i >> 4;
    float di = g_dinv[n];
    g_agg16[i] = x16[i] * di * di;
}
__global__ void k_up_scatter(const int* __restrict__ es, const int* __restrict__ ed,
                             const float* __restrict__ x16) {
    int i = blockIdx.x * blockDim.x + threadIdx.x;
    if (i >= NE_UP * 4) return;
    int e = i >> 2, q = i & 3;
    int s = es[e], d = ed[e];
    float norm = g_dinv[s] * g_dinv[d];
    float4 v = ((const float4*)(x16 + (size_t)s * 16))[q];
    v.x *= norm; v.y *= norm; v.z *= norm; v.w *= norm;
    red_add_v4(g_agg16 + (size_t)d * 16 + q * 4, v);
}

// ---------------- generic conv aggregation ----------------
__global__ void k_agg_init(const float* __restrict__ stat, int dslot, int mask_il) {
    int tid = threadIdx.x;
    int c = tid % 72, r = tid / 72;
    int idx = blockIdx.x * 4 + r;
    int cnt = (mask_il >= 0) ? g_cnt[mask_il] : Nn;
    if (idx >= cnt) return;
    int n = (mask_il >= 0) ? g_rows[(size_t)mask_il * Nn + idx] : idx;
    float di = g_dinv[(size_t)dslot * Nn + n];
    float s = di * di;
    float4 v = (c < 64) ? ((const float4*)(g_x + (size_t)n * F))[c]
                        : ((const float4*)(stat + (size_t)n * FS))[c - 64];
    v.x *= s; v.y *= s; v.z *= s; v.w *= s;
    ((float4*)(g_agg + (size_t)n * FA))[c] = v;
}
__global__ void k_scatter(const int* __restrict__ es, const int* __restrict__ ed,
                          int dslot, const float* __restrict__ stat,
                          const int* __restrict__ layers, int mask_il) {
    int w = (blockIdx.x * blockDim.x + threadIdx.x) >> 5;
    int lane = threadIdx.x & 31;
    if (w >= NE_L) return;
    int d = ed[w];
    if (mask_il >= 0 && layers[d] != mask_il) return;
    int s = es[w];
    const float* dinv = g_dinv + (size_t)dslot * Nn;
    float norm = dinv[s] * dinv[d];
    const float4* xs = (const float4*)(g_x + (size_t)s * F);
    const float4* ss = (const float4*)(stat + (size_t)s * FS);
    float* aggd = g_agg + (size_t)d * FA;
    for (int c = lane; c < 72; c += 32) {
        float4 v = (c < 64) ? xs[c] : ss[c - 64];
        v.x *= norm; v.y *= norm; v.z *= norm; v.w *= norm;
        red_add_v4(aggd + c * 4, v);
    }
}

// ---------------- tensor-core tf32 GEMM (mma.sync) ----------------
// out[rows, colblk] = A[rows,Ktot] @ B^T + bias ; B = Wt[256,Ktot] (col-major of W)
// block: 256 thr (8 warps = 2M x 4N), tile M=128 N=128, K-chunks of 32.
#define KC 32
#define ASTRIDE 36   // 32 + 4 pad: fragment LDS is bank-conflict-free

__global__ void __launch_bounds__(256)
k_mma_gemm(const float* __restrict__ A, int astride, int Ktot,
           const float* __restrict__ Wt, const float* __restrict__ bias,
           int mask_il, int to_pi) {
    __shared__ uint32_t As[128 * ASTRIDE];
    __shared__ uint32_t Bs[128 * ASTRIDE];

    int cnt = (mask_il >= 0) ? g_cnt[mask_il] : Nn;
    const int* list = (mask_il >= 0) ? (g_rows + (size_t)mask_il * Nn) : nullptr;
    int row0 = blockIdx.x * 128;
    if (row0 >= cnt) return;
    int colb = blockIdx.y * 128;

    int tid = threadIdx.x, wid = tid >> 5, lane = tid & 31;
    int wm = (wid >> 2) * 64;          // warp M offset (0 or 64)
    int wn = (wid & 3) * 32;           // warp N offset (0..96)
    int q = lane >> 2, t = lane & 3;   // groupID, threadID-in-group

    float acc[4][4][4];
#pragma unroll
    for (int i = 0; i < 4; i++)
#pragma unroll
        for (int j = 0; j < 4; j++)
#pragma unroll
            for (int k = 0; k < 4; k++) acc[i][j][k] = 0.f;

    // A global row per load slot (4 float4 per thread per chunk)
    int amrow[4];
#pragma unroll
    for (int i = 0; i < 4; i++) {
        int m = (tid + i * 256) >> 3;
        int g = row0 + m;
        amrow[i] = (g < cnt) ? (list ? list[g] : g) : (list ? list[row0] : row0);
    }

    for (int kt = 0; kt < Ktot; kt += KC) {
        // ---- stage A chunk: 128 x 32 ----
#pragma unroll
        for (int i = 0; i < 4; i++) {
            int idx = tid + i * 256;
            int m = idx >> 3, k4 = idx & 7;
            uint4 v = make_uint4(0, 0, 0, 0);
            if (kt + k4 * 4 < Ktot) {
                float4 f = *(const float4*)(A + (size_t)amrow[i] * astride + kt + k4 * 4);
                v = make_uint4(f2tf32(f.x), f2tf32(f.y), f2tf32(f.z), f2tf32(f.w));
            }
            uint32_t* p = &As[m * ASTRIDE + k4 * 4];
            p[0] = v.x; p[1] = v.y; p[2] = v.z; p[3] = v.w;
        }
        // ---- stage B chunk: 128 n-rows x 32 k ----
#pragma unroll
        for (int i = 0; i < 4; i++) {
            int idx = tid + i * 256;
            int n = idx >> 3, k4 = idx & 7;
            uint4 v = make_uint4(0, 0, 0, 0);
            if (kt + k4 * 4 < Ktot) {
                float4 f = *(const float4*)(Wt + (size_t)(colb + n) * Ktot + kt + k4 * 4);
                v = make_uint4(f2tf32(f.x), f2tf32(f.y), f2tf32(f.z), f2tf32(f.w));
            }
            uint32_t* p = &Bs[n * ASTRIDE + k4 * 4];
            p[0] = v.x; p[1] = v.y; p[2] = v.z; p[3] = v.w;
        }
        __syncthreads();
#pragma unroll
        for (int ks = 0; ks < 4; ks++) {
            int kc = ks * 8;
            uint32_t af[4][4];
#pragma unroll
            for (int mt = 0; mt < 4; mt++) {
                int r = wm + mt * 16 + q;
                af[mt][0] = As[r * ASTRIDE + kc + t];
                af[mt][1] = As[(r + 8) * ASTRIDE + kc + t];
                af[mt][2] = As[r * ASTRIDE + kc + t + 4];
                af[mt][3] = As[(r + 8) * ASTRIDE + kc + t + 4];
            }
            uint32_t bf[4][2];
#pragma unroll
            for (int nt = 0; nt < 4; nt++) {
                int n = wn + nt * 8 + q;
                bf[nt][0] = Bs[n * ASTRIDE + kc + t];
                bf[nt][1] = Bs[n * ASTRIDE + kc + t + 4];
            }
#pragma unroll
            for (int mt = 0; mt < 4; mt++)
#pragma unroll
                for (int nt = 0; nt < 4; nt++)
                    mma_tf32(acc[mt][nt], af[mt], bf[nt]);
        }
        __syncthreads();
    }

    // ---- epilogue: scatter to output rows ----
    float* outb = to_pi ? g_pi : g_x;
#pragma unroll
    for (int mt = 0; mt < 4; mt++) {
        int g0 = row0 + wm + mt * 16 + q;
        int g1 = g0 + 8;
        int n0 = (g0 < cnt) ? (list ? list[g0] : g0) : -1;
        int n1 = (g1 < cnt) ? (list ? list[g1] : g1) : -1;
#pragma unroll
        for (int nt = 0; nt < 4; nt++) {
            int col = colb + wn + nt * 8 + t * 2;
            float b0 = bias[col], b1 = bias[col + 1];
            if (n0 >= 0) {
                float2 v = make_float2(acc[mt][nt][0] + b0, acc[mt][nt][1] + b1);
                *(float2*)(outb + (size_t)n0 * F + col) = v;
            }
            if (n1 >= 0) {
                float2 v = make_float2(acc[mt][nt][2] + b0, acc[mt][nt][3] + b1);
                *(float2*)(outb + (size_t)n1 * F + col) = v;
            }
        }
    }
}

// ---------------- misc ----------------
__global__ void k_copy_rows(int il) {
    int c = threadIdx.x % 64, r = threadIdx.x / 64;
    int idx = blockIdx.x * 4 + r;
    if (idx >= g_cnt[il]) return;
    int n = g_rows[(size_t)il * Nn + idx];
    ((float4*)(g_x + (size_t)n * F))[c] = ((const float4*)(g_pi + (size_t)n * F))[c];
}
__global__ void k_relu() {
    int i = blockIdx.x * blockDim.x + threadIdx.x;
    if (i < Nn * F) g_x[i] = fmaxf(g_x[i], 0.f);
}
__global__ void k_pool_init(const float* __restrict__ bl, float* __restrict__ out) {
    int g = threadIdx.x;
    if (g < NG) out[g] = bl[0];
}
__global__ void k_pool(const int* __restrict__ batch, const float* __restrict__ Wl,
                       float* __restrict__ out) {
    int w = (blockIdx.x * blockDim.x + threadIdx.x) >> 5;
    int lane = threadIdx.x & 31;
    if (w >= Nn) return;
    const float* xr = g_x + (size_t)w * F;
    float s = 0.f;
    for (int c = lane; c < F; c += 32) s += xr[c] * Wl[c];
#pragma unroll
    for (int o = 16; o; o >>= 1) s += __shfl_down_sync(0xffffffffu, s, o);
    if (lane == 0) atomicAdd(&out[batch[w]], s);
}

// ---------------- orchestration ----------------
extern "C" void kernel_launch(void* const* d_in, const int* in_sizes, int n_in,
                              void* d_out, int out_size) {
    const float* x16    = (const float*)d_in[0];
    const float* stat   = (const float*)d_in[1];
    const int*   eidx   = (const int*)d_in[2];
    const int*   einner = (const int*)d_in[3];
    const int*   efw    = (const int*)d_in[4];
    const int*   layers = (const int*)d_in[6];
    const int*   batch  = (const int*)d_in[7];
    const float* W_up  = (const float*)d_in[8];
    const float* b_up  = (const float*)d_in[9];
    const float* W_in  = (const float*)d_in[10];
    const float* b_in  = (const float*)d_in[11];
    const float* W_fw  = (const float*)d_in[12];
    const float* b_fw  = (const float*)d_in[13];
    const float* W_lin = (const float*)d_in[14];
    const float* b_lin = (const float*)d_in[15];
    float* out = (float*)d_out;

    float* d_WtIn; cudaGetSymbolAddress((void**)&d_WtIn, g_WtIn);
    float* d_WtFw; cudaGetSymbolAddress((void**)&d_WtFw, g_WtFw);
    float* d_WtUp; cudaGetSymbolAddress((void**)&d_WtUp, g_WtUp);
    float* d_agg;  cudaGetSymbolAddress((void**)&d_agg,  g_agg);
    float* d_agg16;cudaGetSymbolAddress((void**)&d_agg16,g_agg16);

    // ---- setup ----
    k_deg_init<<<(9 * Nn + 255) / 256, 256>>>();
    k_deg_count<<<(NE_UP + 255) / 256, 256>>>(eidx + NE_UP, NE_UP, 0);
    for (int il = 0; il < NLY; il++)
        k_deg_count<<<(NE_L + 255) / 256, 256>>>(einner + (size_t)il * 2 * NE_L + NE_L, NE_L, 1 + il);
    for (int il = 0; il < NLY; il++)
        k_deg_count<<<(NE_L + 255) / 256, 256>>>(efw + (size_t)il * 2 * NE_L + NE_L, NE_L, 5 + il);
    k_rsqrt<<<(9 * Nn + 255) / 256, 256>>>();
    k_build<<<(Nn + 255) / 256, 256>>>(layers);
    k_transpose<<<(FA * 256 + 255) / 256, 256>>>(W_in, d_WtIn, FA);
    k_transpose<<<(FA * 256 + 255) / 256, 256>>>(W_fw, d_WtFw, FA);
    k_transpose<<<(16 * 256 + 255) / 256, 256>>>(W_up, d_WtUp, 16);

    const int GX = (Nn + 127) / 128;

    // ---- up conv ----
    k_up_init<<<(Nn * 16 + 255) / 256, 256>>>(x16);
    k_up_scatter<<<(NE_UP * 4 + 255) / 256, 256>>>(eidx, eidx + NE_UP, x16);
    k_mma_gemm<<<dim3(GX, 2), 256>>>(d_agg16, 16, 16, d_WtUp, b_up, -1, 0);

    auto conv = [&](const int* es, const int* ed, int dslot, int mask,
                    const float* Wt, const float* bb, int to_pi) {
        k_agg_init<<<(Nn + 3) / 4, 288>>>(stat, dslot, mask);
        k_scatter<<<(NE_L * 32 + 255) / 256, 256>>>(es, ed, dslot, stat, layers, mask);
        k_mma_gemm<<<dim3(GX, 2), 256>>>(d_agg, FA, FA, Wt, bb, mask, to_pi);
    };
    auto in_src = [&](int il) { return einner + (size_t)il * 2 * NE_L; };
    auto fw_src = [&](int il) { return efw + (size_t)il * 2 * NE_L; };

    for (int p = 0; p < 2; p++) {
        for (int il = 0; il < 3; il++) {
            conv(in_src(il), in_src(il) + NE_L, 1 + il, il, d_WtIn, b_in, 0);
            conv(fw_src(il), fw_src(il) + NE_L, 5 + il, il + 1, d_WtFw, b_fw, 0);
        }
        conv(in_src(3), in_src(3) + NE_L, 4, -1, d_WtIn, b_in, 1);   // full -> pi
        k_copy_rows<<<(Nn + 3) / 4, 256>>>(3);
        k_relu<<<(Nn * F + 255) / 256, 256>>>();
        for (int il = 3; il >= 0; il--) {
            if (il >= 1) k_copy_rows<<<(Nn + 3) / 4, 256>>>(il - 1);
            conv(in_src(il), in_src(il) + NE_L, 1 + il, il, d_WtIn, b_in, 0);
        }
        k_relu<<<(Nn * F + 255) / 256, 256>>>();
    }

    k_pool_init<<<1, 64>>>(b_lin, out);
    k_pool<<<(Nn * 32 + 255) / 256, 256>>>(batch, W_lin, out);
}

// round 4
// speedup vs baseline: 2.1577x; 1.4818x over previous
#include <cuda_runtime.h>
#include <cstdint>

#define Nn    100000
#define F     256
#define FS    32
#define FA    288
#define NLY   4
#define NG    50
#define NE_UP 400000
#define NE_L  300000
#define NE_TOT (NE_UP + 8 * NE_L)      // 2.8M
#define SCAN_L (9 * Nn)                 // 900000
#define SCAN_BLK 1024
#define SCAN_NB ((SCAN_L + SCAN_BLK - 1) / SCAN_BLK)   // 879

// ---------------- device scratch ----------------
__device__ float g_x[(size_t)Nn * F];
__device__ float g_pi[(size_t)Nn * F];
__device__ float g_agg[(size_t)Nn * FA];
__device__ float g_agg16[(size_t)Nn * 16];
__device__ float g_dinv[(size_t)SCAN_L];
__device__ int   g_hist[(size_t)SCAN_L];     // histogram, then fill-cursor
__device__ int   g_rp[(size_t)SCAN_L + 1];   // CSR row pointers (global across 9 slots)
__device__ int   g_col[(size_t)NE_TOT];      // src indices, dst-sorted
__device__ float g_we[(size_t)NE_TOT];       // dinv[src] per edge
__device__ int   g_bsum[SCAN_NB];
__device__ int   g_boff[SCAN_NB];
__device__ int   g_total;
__device__ int   g_rows[(size_t)NLY * Nn];
__device__ int   g_cnt[NLY];
__device__ float g_WtIn[(size_t)256 * FA];
__device__ float g_WtFw[(size_t)256 * FA];
__device__ float g_WtUp[(size_t)256 * 16];

__device__ __forceinline__ uint32_t f2tf32(float f) {
    uint32_t r; asm("cvt.rna.tf32.f32 %0, %1;" : "=r"(r) : "f"(f)); return r;
}
__device__ __forceinline__ void mma_tf32(float* d, const uint32_t* a, const uint32_t* b) {
    asm volatile(
        "mma.sync.aligned.m16n8k8.row.col.f32.tf32.tf32.f32 "
        "{%0,%1,%2,%3}, {%4,%5,%6,%7}, {%8,%9}, {%0,%1,%2,%3};"
        : "+f"(d[0]), "+f"(d[1]), "+f"(d[2]), "+f"(d[3])
        : "r"(a[0]), "r"(a[1]), "r"(a[2]), "r"(a[3]), "r"(b[0]), "r"(b[1]));
}
__device__ __forceinline__ float4 fmaf4(float4 a, float w, float4 v) {
    a.x = fmaf(w, v.x, a.x); a.y = fmaf(w, v.y, a.y);
    a.z = fmaf(w, v.z, a.z); a.w = fmaf(w, v.w, a.w);
    return a;
}

// ---------------- CSR build ----------------
__global__ void k_hist0() {
    int i = blockIdx.x * blockDim.x + threadIdx.x;
    if (i < SCAN_L) g_hist[i] = 0;
    if (i < NLY) g_cnt[i] = 0;
}
__global__ void k_hist(const int* __restrict__ dst, int nE, int slot) {
    int i = blockIdx.x * blockDim.x + threadIdx.x;
    if (i >= nE) return;
    atomicAdd(&g_hist[(size_t)slot * Nn + dst[i]], 1);
}
// 3-phase exclusive scan over g_hist[SCAN_L] -> g_rp
__global__ void k_scan1() {
    __shared__ int ws[8];
    int t = threadIdx.x;
    int base = blockIdx.x * SCAN_BLK + t * 4;
    int v[4], s = 0;
#pragma unroll
    for (int j = 0; j < 4; j++) {
        v[j] = (base + j < SCAN_L) ? g_hist[base + j] : 0;
        s += v[j];
    }
    int lane = t & 31, w = t >> 5;
    int inc = s;
#pragma unroll
    for (int o = 1; o < 32; o <<= 1) {
        int x = __shfl_up_sync(0xffffffffu, inc, o);
        if (lane >= o) inc += x;
    }
    if (lane == 31) ws[w] = inc;
    __syncthreads();
    if (t < 8) {
        int x = ws[t];
#pragma unroll
        for (int o = 1; o < 8; o <<= 1) {
            int y = __shfl_up_sync(0xffu, x, o);
            if (t >= o) x += y;
        }
        ws[t] = x;
    }
    __syncthreads();
    int run = inc - s + (w > 0 ? ws[w - 1] : 0);
#pragma unroll
    for (int j = 0; j < 4; j++) {
        if (base + j < SCAN_L) g_rp[base + j] = run;
        run += v[j];
    }
    if (t == 0) g_bsum[blockIdx.x] = 0;   // ensure defined
    __syncthreads();
    if (t == 255) g_bsum[blockIdx.x] = ws[7];
}
__global__ void k_scan2() {
    __shared__ int ws[32];
    int t = threadIdx.x;
    int v = (t < SCAN_NB) ? g_bsum[t] : 0;
    int lane = t & 31, w = t >> 5;
    int inc = v;
#pragma unroll
    for (int o = 1; o < 32; o <<= 1) {
        int x = __shfl_up_sync(0xffffffffu, inc, o);
        if (lane >= o) inc += x;
    }
    if (lane == 31) ws[w] = inc;
    __syncthreads();
    if (t < 32) {
        int x = ws[t];
#pragma unroll
        for (int o = 1; o < 32; o <<= 1) {
            int y = __shfl_up_sync(0xffffffffu, x, o);
            if (t >= o) x += y;
        }
        ws[t] = x;
    }
    __syncthreads();
    int excl = inc - v + (w > 0 ? ws[w - 1] : 0);
    if (t < SCAN_NB) g_boff[t] = excl;
    if (t == SCAN_NB - 1) g_total = excl + v;
}
__global__ void k_scan3() {
    int t = threadIdx.x;
    int off = g_boff[blockIdx.x];
    int base = blockIdx.x * SCAN_BLK + t * 4;
#pragma unroll
    for (int j = 0; j < 4; j++)
        if (base + j < SCAN_L) g_rp[base + j] += off;
    if (blockIdx.x == 0 && t == 0) g_rp[SCAN_L] = g_total;
}
__global__ void k_dinv() {
    int i = blockIdx.x * blockDim.x + threadIdx.x;
    if (i < SCAN_L) g_dinv[i] = rsqrtf((float)(g_hist[i] + 1));   // +1 self loop
}
__global__ void k_cursor() {
    int i = blockIdx.x * blockDim.x + threadIdx.x;
    if (i < SCAN_L) g_hist[i] = g_rp[i];
}
__global__ void k_fill(const int* __restrict__ src, const int* __restrict__ dst,
                       int nE, int slot) {
    int e = blockIdx.x * blockDim.x + threadIdx.x;
    if (e >= nE) return;
    int d = dst[e], s = src[e];
    int pos = atomicAdd(&g_hist[(size_t)slot * Nn + d], 1);
    g_col[pos] = s;
    g_we[pos] = g_dinv[(size_t)slot * Nn + s];
}
__global__ void k_build(const int* __restrict__ layers) {
    int n = blockIdx.x * blockDim.x + threadIdx.x;
    if (n >= Nn) return;
    int il = layers[n];
    int p = atomicAdd(&g_cnt[il], 1);
    g_rows[(size_t)il * Nn + p] = n;
}
__global__ void k_transpose(const float* __restrict__ W, float* __restrict__ Wt, int K) {
    int i = blockIdx.x * blockDim.x + threadIdx.x;
    if (i >= K * 256) return;
    int k = i >> 8, n = i & 255;
    Wt[(size_t)n * K + k] = W[i];
}

// ---------------- aggregation: CSR gather (no atomics) ----------------
// warp per destination row; 288 floats = 72 f4 chunks: a0(lane), a1(lane+32), a2(lane+64, lanes<8)
__global__ void __launch_bounds__(256)
k_gather(const float* __restrict__ stat, int slot, int mask_il) {
    int w = threadIdx.x >> 5, lane = threadIdx.x & 31;
    int idx = blockIdx.x * 8 + w;
    int cnt = (mask_il >= 0) ? g_cnt[mask_il] : Nn;
    if (idx >= cnt) return;
    int n = (mask_il >= 0) ? g_rows[(size_t)mask_il * Nn + idx] : idx;
    size_t sb = (size_t)slot * Nn;
    float dd = g_dinv[sb + n];
    int r0 = g_rp[sb + n], r1 = g_rp[sb + n + 1];

    const float4* xn = (const float4*)(g_x + (size_t)n * F);
    float4 a0 = xn[lane], a1 = xn[lane + 32];
    float4 a2 = make_float4(0.f, 0.f, 0.f, 0.f);
    if (lane < 8) a2 = ((const float4*)(stat + (size_t)n * FS))[lane];
    a0.x *= dd; a0.y *= dd; a0.z *= dd; a0.w *= dd;
    a1.x *= dd; a1.y *= dd; a1.z *= dd; a1.w *= dd;
    a2.x *= dd; a2.y *= dd; a2.z *= dd; a2.w *= dd;

    for (int e = r0; e < r1; e++) {
        int s = g_col[e];
        float wgt = g_we[e];
        const float4* xs = (const float4*)(g_x + (size_t)s * F);
        a0 = fmaf4(a0, wgt, xs[lane]);
        a1 = fmaf4(a1, wgt, xs[lane + 32]);
        if (lane < 8)
            a2 = fmaf4(a2, wgt, ((const float4*)(stat + (size_t)s * FS))[lane]);
    }
    a0.x *= dd; a0.y *= dd; a0.z *= dd; a0.w *= dd;
    a1.x *= dd; a1.y *= dd; a1.z *= dd; a1.w *= dd;
    a2.x *= dd; a2.y *= dd; a2.z *= dd; a2.w *= dd;

    float4* ag = (float4*)(g_agg + (size_t)n * FA);
    ag[lane] = a0;
    ag[lane + 32] = a1;
    if (lane < 8) ag[lane + 64] = a2;
}

// up conv: 4 threads per row (16 floats), slot 0
__global__ void k_up_gather(const float* __restrict__ x16) {
    int i = blockIdx.x * blockDim.x + threadIdx.x;
    if (i >= Nn * 4) return;
    int n = i >> 2, q = i & 3;
    float dd = g_dinv[n];
    int r0 = g_rp[n], r1 = g_rp[n + 1];
    float4 a = ((const float4*)(x16 + (size_t)n * 16))[q];
    a.x *= dd; a.y *= dd; a.z *= dd; a.w *= dd;
    for (int e = r0; e < r1; e++) {
        int s = g_col[e];
        float wgt = g_we[e];
        a = fmaf4(a, wgt, ((const float4*)(x16 + (size_t)s * 16))[q]);
    }
    a.x *= dd; a.y *= dd; a.z *= dd; a.w *= dd;
    ((float4*)(g_agg16 + (size_t)n * 16))[q] = a;
}

// ---------------- tensor-core tf32 GEMM (mma.sync) — unchanged from R3 ----------------
#define KC 32
#define ASTRIDE 36

__global__ void __launch_bounds__(256)
k_mma_gemm(const float* __restrict__ A, int astride, int Ktot,
           const float* __restrict__ Wt, const float* __restrict__ bias,
           int mask_il, int to_pi) {
    __shared__ uint32_t As[128 * ASTRIDE];
    __shared__ uint32_t Bs[128 * ASTRIDE];

    int cnt = (mask_il >= 0) ? g_cnt[mask_il] : Nn;
    const int* list = (mask_il >= 0) ? (g_rows + (size_t)mask_il * Nn) : nullptr;
    int row0 = blockIdx.x * 128;
    if (row0 >= cnt) return;
    int colb = blockIdx.y * 128;

    int tid = threadIdx.x, wid = tid >> 5, lane = tid & 31;
    int wm = (wid >> 2) * 64;
    int wn = (wid & 3) * 32;
    int q = lane >> 2, t = lane & 3;

    float acc[4][4][4];
#pragma unroll
    for (int i = 0; i < 4; i++)
#pragma unroll
        for (int j = 0; j < 4; j++)
#pragma unroll
            for (int k = 0; k < 4; k++) acc[i][j][k] = 0.f;

    int amrow[4];
#pragma unroll
    for (int i = 0; i < 4; i++) {
        int m = (tid + i * 256) >> 3;
        int g = row0 + m;
        amrow[i] = (g < cnt) ? (list ? list[g] : g) : (list ? list[row0] : row0);
    }

    for (int kt = 0; kt < Ktot; kt += KC) {
#pragma unroll
        for (int i = 0; i < 4; i++) {
            int idx = tid + i * 256;
            int m = idx >> 3, k4 = idx & 7;
            uint4 v = make_uint4(0, 0, 0, 0);
            if (kt + k4 * 4 < Ktot) {
                float4 f = *(const float4*)(A + (size_t)amrow[i] * astride + kt + k4 * 4);
                v = make_uint4(f2tf32(f.x), f2tf32(f.y), f2tf32(f.z), f2tf32(f.w));
            }
            uint32_t* p = &As[m * ASTRIDE + k4 * 4];
            p[0] = v.x; p[1] = v.y; p[2] = v.z; p[3] = v.w;
        }
#pragma unroll
        for (int i = 0; i < 4; i++) {
            int idx = tid + i * 256;
            int n = idx >> 3, k4 = idx & 7;
            uint4 v = make_uint4(0, 0, 0, 0);
            if (kt + k4 * 4 < Ktot) {
                float4 f = *(const float4*)(Wt + (size_t)(colb + n) * Ktot + kt + k4 * 4);
                v = make_uint4(f2tf32(f.x), f2tf32(f.y), f2tf32(f.z), f2tf32(f.w));
            }
            uint32_t* p = &Bs[n * ASTRIDE + k4 * 4];
            p[0] = v.x; p[1] = v.y; p[2] = v.z; p[3] = v.w;
        }
        __syncthreads();
#pragma unroll
        for (int ks = 0; ks < 4; ks++) {
            int kc = ks * 8;
            uint32_t af[4][4];
#pragma unroll
            for (int mt = 0; mt < 4; mt++) {
                int r = wm + mt * 16 + q;
                af[mt][0] = As[r * ASTRIDE + kc + t];
                af[mt][1] = As[(r + 8) * ASTRIDE + kc + t];
                af[mt][2] = As[r * ASTRIDE + kc + t + 4];
                af[mt][3] = As[(r + 8) * ASTRIDE + kc + t + 4];
            }
            uint32_t bf[4][2];
#pragma unroll
            for (int nt = 0; nt < 4; nt++) {
                int n = wn + nt * 8 + q;
                bf[nt][0] = Bs[n * ASTRIDE + kc + t];
                bf[nt][1] = Bs[n * ASTRIDE + kc + t + 4];
            }
#pragma unroll
            for (int mt = 0; mt < 4; mt++)
#pragma unroll
                for (int nt = 0; nt < 4; nt++)
                    mma_tf32(acc[mt][nt], af[mt], bf[nt]);
        }
        __syncthreads();
    }

    float* outb = to_pi ? g_pi : g_x;
#pragma unroll
    for (int mt = 0; mt < 4; mt++) {
        int g0 = row0 + wm + mt * 16 + q;
        int g1 = g0 + 8;
        int n0 = (g0 < cnt) ? (list ? list[g0] : g0) : -1;
        int n1 = (g1 < cnt) ? (list ? list[g1] : g1) : -1;
#pragma unroll
        for (int nt = 0; nt < 4; nt++) {
            int col = colb + wn + nt * 8 + t * 2;
            float b0 = bias[col], b1 = bias[col + 1];
            if (n0 >= 0) {
                float2 v = make_float2(acc[mt][nt][0] + b0, acc[mt][nt][1] + b1);
                *(float2*)(outb + (size_t)n0 * F + col) = v;
            }
            if (n1 >= 0) {
                float2 v = make_float2(acc[mt][nt][2] + b0, acc[mt][nt][3] + b1);
                *(float2*)(outb + (size_t)n1 * F + col) = v;
            }
        }
    }
}

// ---------------- misc ----------------
__global__ void k_copy_rows(int il) {
    int c = threadIdx.x % 64, r = threadIdx.x / 64;
    int idx = blockIdx.x * 4 + r;
    if (idx >= g_cnt[il]) return;
    int n = g_rows[(size_t)il * Nn + idx];
    ((float4*)(g_x + (size_t)n * F))[c] = ((const float4*)(g_pi + (size_t)n * F))[c];
}
__global__ void k_relu4() {
    int i = blockIdx.x * blockDim.x + threadIdx.x;
    if (i >= Nn * F / 4) return;
    float4* p = (float4*)g_x;
    float4 v = p[i];
    v.x = fmaxf(v.x, 0.f); v.y = fmaxf(v.y, 0.f);
    v.z = fmaxf(v.z, 0.f); v.w = fmaxf(v.w, 0.f);
    p[i] = v;
}
__global__ void k_pool_init(const float* __restrict__ bl, float* __restrict__ out) {
    int g = threadIdx.x;
    if (g < NG) out[g] = bl[0];
}
__global__ void k_pool(const int* __restrict__ batch, const float* __restrict__ Wl,
                       float* __restrict__ out) {
    int w = (blockIdx.x * blockDim.x + threadIdx.x) >> 5;
    int lane = threadIdx.x & 31;
    if (w >= Nn) return;
    const float* xr = g_x + (size_t)w * F;
    float s = 0.f;
    for (int c = lane; c < F; c += 32) s += xr[c] * Wl[c];
#pragma unroll
    for (int o = 16; o; o >>= 1) s += __shfl_down_sync(0xffffffffu, s, o);
    if (lane == 0) atomicAdd(&out[batch[w]], s);
}

// ---------------- orchestration ----------------
extern "C" void kernel_launch(void* const* d_in, const int* in_sizes, int n_in,
                              void* d_out, int out_size) {
    const float* x16    = (const float*)d_in[0];
    const float* stat   = (const float*)d_in[1];
    const int*   eidx   = (const int*)d_in[2];
    const int*   einner = (const int*)d_in[3];
    const int*   efw    = (const int*)d_in[4];
    const int*   layers = (const int*)d_in[6];
    const int*   batch  = (const int*)d_in[7];
    const float* W_up  = (const float*)d_in[8];
    const float* b_up  = (const float*)d_in[9];
    const float* W_in  = (const float*)d_in[10];
    const float* b_in  = (const float*)d_in[11];
    const float* W_fw  = (const float*)d_in[12];
    const float* b_fw  = (const float*)d_in[13];
    const float* W_lin = (const float*)d_in[14];
    const float* b_lin = (const float*)d_in[15];
    float* out = (float*)d_out;

    float* d_WtIn; cudaGetSymbolAddress((void**)&d_WtIn, g_WtIn);
    float* d_WtFw; cudaGetSymbolAddress((void**)&d_WtFw, g_WtFw);
    float* d_WtUp; cudaGetSymbolAddress((void**)&d_WtUp, g_WtUp);
    float* d_agg;  cudaGetSymbolAddress((void**)&d_agg,  g_agg);
    float* d_agg16;cudaGetSymbolAddress((void**)&d_agg16,g_agg16);

    // ---- CSR build for all 9 edge sets ----
    k_hist0<<<(SCAN_L + 255) / 256, 256>>>();
    k_hist<<<(NE_UP + 255) / 256, 256>>>(eidx + NE_UP, NE_UP, 0);
    for (int il = 0; il < NLY; il++)
        k_hist<<<(NE_L + 255) / 256, 256>>>(einner + (size_t)il * 2 * NE_L + NE_L, NE_L, 1 + il);
    for (int il = 0; il < NLY; il++)
        k_hist<<<(NE_L + 255) / 256, 256>>>(efw + (size_t)il * 2 * NE_L + NE_L, NE_L, 5 + il);
    k_scan1<<<SCAN_NB, 256>>>();
    k_scan2<<<1, 1024>>>();
    k_scan3<<<SCAN_NB, 256>>>();
    k_dinv<<<(SCAN_L + 255) / 256, 256>>>();
    k_cursor<<<(SCAN_L + 255) / 256, 256>>>();
    k_fill<<<(NE_UP + 255) / 256, 256>>>(eidx, eidx + NE_UP, NE_UP, 0);
    for (int il = 0; il < NLY; il++)
        k_fill<<<(NE_L + 255) / 256, 256>>>(einner + (size_t)il * 2 * NE_L,
                                            einner + (size_t)il * 2 * NE_L + NE_L, NE_L, 1 + il);
    for (int il = 0; il < NLY; il++)
        k_fill<<<(NE_L + 255) / 256, 256>>>(efw + (size_t)il * 2 * NE_L,
                                            efw + (size_t)il * 2 * NE_L + NE_L, NE_L, 5 + il);
    k_build<<<(Nn + 255) / 256, 256>>>(layers);
    k_transpose<<<(FA * 256 + 255) / 256, 256>>>(W_in, d_WtIn, FA);
    k_transpose<<<(FA * 256 + 255) / 256, 256>>>(W_fw, d_WtFw, FA);
    k_transpose<<<(16 * 256 + 255) / 256, 256>>>(W_up, d_WtUp, 16);

    const int GX = (Nn + 127) / 128;

    // ---- up conv ----
    k_up_gather<<<(Nn * 4 + 255) / 256, 256>>>(x16);
    k_mma_gemm<<<dim3(GX, 2), 256>>>(d_agg16, 16, 16, d_WtUp, b_up, -1, 0);

    auto conv = [&](int slot, int mask, const float* Wt, const float* bb, int to_pi) {
        k_gather<<<(Nn + 7) / 8, 256>>>(stat, slot, mask);
        k_mma_gemm<<<dim3(GX, 2), 256>>>(d_agg, FA, FA, Wt, bb, mask, to_pi);
    };

    for (int p = 0; p < 2; p++) {
        for (int il = 0; il < 3; il++) {
            conv(1 + il, il, d_WtIn, b_in, 0);          // inner -> rows(il)
            conv(5 + il, il + 1, d_WtFw, b_fw, 0);      // fw    -> rows(il+1)
        }
        conv(4, -1, d_WtIn, b_in, 1);                    // inner il=3, full -> pi
        k_copy_rows<<<(Nn + 3) / 4, 256>>>(3);
        k_relu4<<<(Nn * F / 4 + 255) / 256, 256>>>();
        for (int il = 3; il >= 0; il--) {
            if (il >= 1) k_copy_rows<<<(Nn + 3) / 4, 256>>>(il - 1);
            conv(1 + il, il, d_WtIn, b_in, 0);
        }
        k_relu4<<<(Nn * F / 4 + 255) / 256, 256>>>();
    }

    k_pool_init<<<1, 64>>>(b_lin, out);
    k_pool<<<(Nn * 32 + 255) / 256, 256>>>(batch, W_lin, out);
}